// round 6
// baseline (speedup 1.0000x reference)
#include <cuda_runtime.h>
#include <cuda_bf16.h>
#include <cstdint>

#define Bn 256
#define Sn 2048
#define Tn 32
#define NCH 64
#define FULLMASK 0xffffffffu
#define LOG32F 3.4657359027997265f

// Scratch (device globals are the sanctioned scratch mechanism)
__device__ unsigned char g_hist[(size_t)Bn * (Sn - 1) * Tn];  // backpointers
__device__ unsigned char g_map[Bn][NCH][Tn];                  // chunk tag maps
__device__ unsigned char g_ent[Bn][NCH];                      // chunk entry tags
__device__ float g_den[Bn];
__device__ float g_num[Bn];
__device__ int   g_last[Bn];

// ---- packed f32x2 helpers (Blackwell) -------------------------------------
__device__ __forceinline__ float2 fadd2(float2 a, float2 b) {
    union { float2 f; unsigned long long u; } A, B, R;
    A.f = a; B.f = b;
    asm("add.rn.f32x2 %0, %1, %2;" : "=l"(R.u) : "l"(A.u), "l"(B.u));
    return R.f;
}
__device__ __forceinline__ float2 ffma2(float2 a, float2 b, float2 c) {
    union { float2 f; unsigned long long u; } A, B, C, R;
    A.f = a; B.f = b; C.f = c;
    asm("fma.rn.f32x2 %0, %1, %2, %3;" : "=l"(R.u) : "l"(A.u), "l"(B.u), "l"(C.u));
    return R.f;
}

// ---- cp.async helpers ------------------------------------------------------
__device__ __forceinline__ uint32_t smem_u32(const void* p) {
    return (uint32_t)__cvta_generic_to_shared(p);
}
__device__ __forceinline__ void cp4(uint32_t d, const void* s) {
    asm volatile("cp.async.ca.shared.global [%0], [%1], 4;" :: "r"(d), "l"(s));
}
#define CP_COMMIT() asm volatile("cp.async.commit_group;")
#define CP_WAIT10() asm volatile("cp.async.wait_group 10;")

// prefetch ring: 16 stages, issue 12 ahead, wait leaves <=10 pending
#define RD 12

// ---------------------------------------------------------------------------
// Dual-chain loop: forward + viterbi for the SAME batch in one warp.
// The two dependency chains are independent -> each fills the other's stalls.
// One shared em ring, one shared __syncwarp, one shared mask.
// ---------------------------------------------------------------------------
template<bool AM>
__device__ __forceinline__ void dual_loop(const float* __restrict__ em, int j,
                                          float* __restrict__ bufF,
                                          float* __restrict__ bufV,
                                          float* __restrict__ ringw,
                                          const signed char* __restrict__ mk,
                                          const float* __restrict__ sTrans,
                                          const float* __restrict__ startv,
                                          const float* __restrict__ endv,
                                          const float* __restrict__ trans,
                                          int b)
{
    // fwd constants: exp(trans)/32 ; vit constants: trans (raw)
    float2 tcF[16], tcV[16];
    #pragma unroll
    for (int k = 0; k < 16; ++k) {
        float2 r, e;
        r.x = trans[(2 * k + 0) * Tn + j];
        r.y = trans[(2 * k + 1) * Tn + j];
        e.x = __expf(r.x) * 0.03125f;
        e.y = __expf(r.y) * 0.03125f;
        tcV[k] = r;
        tcF[k] = e;
    }

    const uint32_t rbase = smem_u32(ringw);
    #pragma unroll
    for (int p = 1; p <= RD; ++p) {
        cp4(rbase + (((p & 15) * 32 + j) << 2), em + (size_t)p * Tn + j);
        CP_COMMIT();
    }

    const float em0 = em[j];
    float s  = __expf(startv[j] + em0);   // fwd state (linear domain)
    float Lr = 0.f;
    int   nm = 0;
    float v  = startv[j] + em0;           // vit state (log domain)
    unsigned char* hb = g_hist + (size_t)b * (Sn - 1) * Tn;

    #pragma unroll 2
    for (int t = 1; t < Sn; ++t) {
        CP_WAIT10();
        float* sb = bufF + (t & 1) * 32;
        float* vb = bufV + (t & 1) * 32;
        sb[j] = s;
        vb[j] = v;
        __syncwarp();
        const float emt = ringw[(t & 15) * 32 + j];
        const float ee  = __expf(emt);

        // ---------------- forward matvec (chain A) -------------------------
        float2 a0 = {0.f, 0.f}, a1 = {0.f, 0.f}, a2 = {0.f, 0.f}, a3 = {0.f, 0.f};
        #pragma unroll
        for (int k = 0; k < 4; ++k) {
            const float4 qa = *(const float4*)(sb + 8 * k);
            const float4 qb = *(const float4*)(sb + 8 * k + 4);
            a0 = ffma2(make_float2(qa.x, qa.y), tcF[4 * k + 0], a0);
            a1 = ffma2(make_float2(qa.z, qa.w), tcF[4 * k + 1], a1);
            a2 = ffma2(make_float2(qb.x, qb.y), tcF[4 * k + 2], a2);
            a3 = ffma2(make_float2(qb.z, qb.w), tcF[4 * k + 3], a3);
        }
        const float2 a01 = fadd2(a0, a1);
        const float2 a23 = fadd2(a2, a3);
        const float2 aa  = fadd2(a01, a23);
        const float ns = (aa.x + aa.y) * ee;

        // ---------------- viterbi step (chain B) ---------------------------
        float tv[16];
        #pragma unroll
        for (int k = 0; k < 8; ++k) {
            const float4 q = *(const float4*)(vb + 4 * k);
            const float2 pa = fadd2(make_float2(q.x, q.y), tcV[2 * k + 0]);
            const float2 pb = fadd2(make_float2(q.z, q.w), tcV[2 * k + 1]);
            tv[2 * k + 0] = fmaxf(pa.x, pa.y);
            tv[2 * k + 1] = fmaxf(pb.x, pb.y);
        }
        float u0 = fmaxf(tv[0], tv[1]),  u1 = fmaxf(tv[2], tv[3]);
        float u2 = fmaxf(tv[4], tv[5]),  u3 = fmaxf(tv[6], tv[7]);
        float u4 = fmaxf(tv[8], tv[9]),  u5 = fmaxf(tv[10], tv[11]);
        float u6 = fmaxf(tv[12], tv[13]), u7 = fmaxf(tv[14], tv[15]);
        float w0 = fmaxf(u0, u1), w1 = fmaxf(u2, u3);
        float w2 = fmaxf(u4, u5), w3 = fmaxf(u6, u7);
        const float m = fmaxf(fmaxf(w0, w1), fmaxf(w2, w3));

        // first pair with pair-max == m (first-occurrence argmax, off-chain)
        int p = 15;
        #pragma unroll
        for (int i = 14; i >= 0; --i)
            p = (tv[i] == m) ? i : p;
        // within-pair winner recomputed from SMEM (conflict-free)
        const float ca = vb[2 * p]     + sTrans[(2 * p) * Tn + j];
        const float cb = vb[2 * p + 1] + sTrans[(2 * p + 1) * Tn + j];
        const int bi = 2 * p + ((cb > ca) ? 1 : 0);
        const float nv = m + emt;

        // ---------------- commit both states -------------------------------
        if (AM) {
            s = ns;
            v = nv;
            hb[(size_t)(t - 1) * Tn + j] = (unsigned char)bi;
        } else {
            const int m_ = mk[t];
            s = m_ ? ns : s;
            nm += (m_ != 0);
            const int bp = m_ ? bi : j;
            v = m_ ? nv : v;
            hb[(size_t)(t - 1) * Tn + j] = (unsigned char)bp;
        }

        // shared ring refill (clamped tail keeps group accounting uniform)
        const int tf = t + RD;
        const int tcl = tf < Sn - 1 ? tf : Sn - 1;
        cp4(rbase + ((((tf & 15) * 32) + j) << 2), em + (size_t)tcl * Tn + j);
        CP_COMMIT();

        if ((t & 15) == 15) {                           // fwd renorm, amortized
            const float r  = __shfl_sync(FULLMASK, s, 0);
            const float rr = __frcp_rn(r);
            s *= rr;
            Lr -= __logf(rr);
        }
    }

    // ---------------- epilogues --------------------------------------------
    if (AM) nm = Sn - 1;
    float dv = s * __expf(endv[j]);
    #pragma unroll
    for (int off = 16; off; off >>= 1)
        dv += __shfl_xor_sync(FULLMASK, dv, off);
    if (j == 0) g_den[b] = (float)nm * LOG32F + Lr + __logf(dv);

    float bv = v + endv[j];
    int   bidx = j;
    #pragma unroll
    for (int off = 16; off; off >>= 1) {
        const float ov = __shfl_xor_sync(FULLMASK, bv, off);
        const int   oi = __shfl_xor_sync(FULLMASK, bidx, off);
        const bool take = (ov > bv) || (ov == bv && oi < bidx);
        bv   = take ? ov : bv;
        bidx = take ? oi : bidx;
    }
    if (j == 0) g_last[b] = bidx;
}

// ---------------------------------------------------------------------------
// Main kernel: 128 CTAs x 64 threads (2 warps). Warp w handles batch
// 2*bid + w, running BOTH its forward and viterbi chains interleaved.
// ---------------------------------------------------------------------------
__global__ __launch_bounds__(64)
void crf_main_kernel(const float* __restrict__ pred,
                     const int*   __restrict__ amask,
                     const float* __restrict__ startv,
                     const float* __restrict__ endv,
                     const float* __restrict__ trans)
{
    const int wib = threadIdx.x >> 5;
    const int j   = threadIdx.x & 31;
    const int b   = (blockIdx.x << 1) | wib;

    __shared__ __align__(16) float ring[2][16][32];
    __shared__ __align__(16) float bufF[2][2][32];
    __shared__ __align__(16) float bufV[2][2][32];
    __shared__ __align__(16) float sTrans[Tn * Tn];
    __shared__ signed char mkS[2][Sn];
    __shared__ int s_allones[2];

    // mask load + all-ones detect (per warp)
    {
        const int* am = amask + (size_t)b * Sn;
        int okv = 1;
        for (int t = j; t < Sn; t += 32) {
            const int mv = am[t];
            mkS[wib][t] = (signed char)mv;
            okv &= (mv == 1);
        }
        const bool ao = __all_sync(FULLMASK, okv != 0);
        if (j == 0) s_allones[wib] = ao ? 1 : 0;
    }
    // trans tile: each warp loads 16 rows
    {
        const int r0 = wib * 16;
        #pragma unroll
        for (int k = 0; k < 16; ++k)
            sTrans[(r0 + k) * Tn + j] = trans[(r0 + k) * Tn + j];
    }
    __syncthreads();

    const float* em = pred + (size_t)b * Sn * Tn;
    if (s_allones[wib])
        dual_loop<true >(em, j, &bufF[wib][0][0], &bufV[wib][0][0],
                         &ring[wib][0][0], mkS[wib], sTrans, startv, endv, trans, b);
    else
        dual_loop<false>(em, j, &bufF[wib][0][0], &bufV[wib][0][0],
                         &ring[wib][0][0], mkS[wib], sTrans, startv, endv, trans, b);
}

// ---------------------------------------------------------------------------
// Backtrace phase 1 (+ numerator blocks): blocks 0..1023 compute per-chunk
// tag maps; blocks 1024..1087 compute the numerator (4 batches each).
// ---------------------------------------------------------------------------
__global__ __launch_bounds__(128)
void bt_phase1(const float* __restrict__ pred,
               const int*   __restrict__ amask,
               const int*   __restrict__ labels,
               const float* __restrict__ startv,
               const float* __restrict__ endv,
               const float* __restrict__ trans)
{
    const int wib  = threadIdx.x >> 5;
    const int lane = threadIdx.x & 31;

    if (blockIdx.x >= (Bn * NCH) / 4) {
        // ------- Numerator: one warp per batch ------------------------------
        const int b = ((int)blockIdx.x - (Bn * NCH) / 4) * 4 + wib;
        const float* em = pred + (size_t)b * Sn * Tn;
        const int* lab = labels + (size_t)b * Sn;
        const int* am  = amask  + (size_t)b * Sn;
        float sum = 0.f;
        int   msum = 0;
        for (int t = lane; t < Sn; t += 32) {
            const int mt = am[t];
            msum += mt;
            const int tg = lab[t];
            if (t == 0) {
                sum += startv[tg] + em[tg];
            } else {
                const int tp = lab[t - 1];
                sum += (trans[tp * Tn + tg] + em[(size_t)t * Tn + tg]) * (float)mt;
            }
        }
        #pragma unroll
        for (int off = 16; off; off >>= 1) {
            sum  += __shfl_xor_sync(FULLMASK, sum, off);
            msum += __shfl_xor_sync(FULLMASK, msum, off);
        }
        if (lane == 0) {
            const int se = msum - 1;
            const int lt = lab[se];
            g_num[b] = sum + endv[lt];
        }
        return;
    }

    const int gw = (blockIdx.x << 2) | wib;       // 0 .. Bn*NCH-1
    const int b = gw >> 6;
    const int c = gw & 63;
    const int lo = c * 32;
    int hi = lo + 31; if (hi > Sn - 2) hi = Sn - 2;
    const int n = hi - lo + 1;

    __shared__ __align__(16) unsigned char sm[4][32 * Tn];
    unsigned char* S = sm[wib];
    const uint32_t* src = (const uint32_t*)(g_hist + ((size_t)b * (Sn - 1) + lo) * Tn);
    uint32_t* dst = (uint32_t*)S;
    for (int i = lane; i < n * 8; i += 32) dst[i] = src[i];
    __syncwarp();

    int tag = lane;
    for (int k = n - 1; k >= 0; --k) tag = S[k * Tn + tag];
    g_map[b][c][lane] = (unsigned char)tag;
}

// ---------------------------------------------------------------------------
// Backtrace phase 2: per batch, compose the 64 chunk maps from the top.
// ---------------------------------------------------------------------------
__global__ __launch_bounds__(128)
void bt_phase2(float* __restrict__ out)
{
    const int wib  = threadIdx.x >> 5;
    const int lane = threadIdx.x & 31;
    const int b = (blockIdx.x << 2) | wib;

    __shared__ __align__(16) unsigned char sm[4][NCH * Tn];
    __shared__ unsigned char se[4][NCH];
    unsigned char* S = sm[wib];
    const uint32_t* src = (const uint32_t*)&g_map[b][0][0];
    uint32_t* dst = (uint32_t*)S;
    for (int i = lane; i < NCH * Tn / 4; i += 32) dst[i] = src[i];
    __syncwarp();

    if (lane == 0) {
        int e = g_last[b];
        out[(size_t)b * Sn + (Sn - 1)] = (float)e;
        for (int c = NCH - 1; c >= 0; --c) {
            se[wib][c] = (unsigned char)e;   // entry tag for chunk c
            e = S[c * Tn + e];               // exit = map[entry]
        }
    }
    __syncwarp();
    for (int c = lane; c < NCH; c += 32) g_ent[b][c] = se[wib][c];
}

// ---------------------------------------------------------------------------
// Backtrace phase 3: re-chase each chunk from its entry tag; coalesced write.
// ---------------------------------------------------------------------------
__global__ __launch_bounds__(128)
void bt_phase3(float* __restrict__ out)
{
    const int wib  = threadIdx.x >> 5;
    const int lane = threadIdx.x & 31;
    const int gw = (blockIdx.x << 2) | wib;
    const int b = gw >> 6;
    const int c = gw & 63;
    const int lo = c * 32;
    int hi = lo + 31; if (hi > Sn - 2) hi = Sn - 2;
    const int n = hi - lo + 1;

    __shared__ __align__(16) unsigned char sm[4][32 * Tn];
    __shared__ unsigned char stag[4][32];
    unsigned char* S = sm[wib];
    const uint32_t* src = (const uint32_t*)(g_hist + ((size_t)b * (Sn - 1) + lo) * Tn);
    uint32_t* dst = (uint32_t*)S;
    for (int i = lane; i < n * 8; i += 32) dst[i] = src[i];
    __syncwarp();

    if (lane == 0) {
        int tag = g_ent[b][c];
        for (int k = n - 1; k >= 0; --k) {
            tag = S[k * Tn + tag];
            stag[wib][k] = (unsigned char)tag;
        }
    }
    __syncwarp();
    if (lane < n) out[(size_t)b * Sn + lo + lane] = (float)stag[wib][lane];
}

// ---------------------------------------------------------------------------
// Loss: -mean(num - den)
// ---------------------------------------------------------------------------
__global__ void crf_loss_kernel(float* __restrict__ out)
{
    __shared__ float red[Bn];
    const int t = threadIdx.x;
    red[t] = g_num[t] - g_den[t];
    __syncthreads();
    #pragma unroll
    for (int off = 128; off; off >>= 1) {
        if (t < off) red[t] += red[t + off];
        __syncthreads();
    }
    if (t == 0) out[(size_t)Bn * Sn] = -(red[0] / (float)Bn);
}

extern "C" void kernel_launch(void* const* d_in, const int* in_sizes, int n_in,
                              void* d_out, int out_size)
{
    const float* pred   = (const float*)d_in[0];
    const int*   amask  = (const int*)  d_in[1];
    const int*   labels = (const int*)  d_in[2];
    const float* startv = (const float*)d_in[3];
    const float* endv   = (const float*)d_in[4];
    const float* trans  = (const float*)d_in[5];
    float* out = (float*)d_out;

    crf_main_kernel<<<128, 64>>>(pred, amask, startv, endv, trans);
    bt_phase1<<<(Bn * NCH) / 4 + Bn / 4, 128>>>(pred, amask, labels, startv, endv, trans);
    bt_phase2<<<Bn / 4, 128>>>(out);
    bt_phase3<<<(Bn * NCH) / 4, 128>>>(out);
    crf_loss_kernel<<<1, Bn>>>(out);
}

// round 7
// speedup vs baseline: 1.1323x; 1.1323x over previous
#include <cuda_runtime.h>
#include <cuda_bf16.h>
#include <cstdint>

#define Bn 256
#define Sn 2048
#define Tn 32
#define NCH 64
#define FULLMASK 0xffffffffu
#define LOG32F 3.4657359027997265f

// Scratch (device globals are the sanctioned scratch mechanism)
__device__ unsigned char g_hist[(size_t)Bn * (Sn - 1) * Tn];  // backpointers
__device__ unsigned char g_map[Bn][NCH][Tn];                  // chunk tag maps
__device__ unsigned char g_ent[Bn][NCH];                      // chunk entry tags
__device__ float g_den[Bn];
__device__ float g_num[Bn];
__device__ int   g_last[Bn];

// ---- packed f32x2 helpers (Blackwell) -------------------------------------
__device__ __forceinline__ float2 fadd2(float2 a, float2 b) {
    union { float2 f; unsigned long long u; } A, B, R;
    A.f = a; B.f = b;
    asm("add.rn.f32x2 %0, %1, %2;" : "=l"(R.u) : "l"(A.u), "l"(B.u));
    return R.f;
}
__device__ __forceinline__ float2 ffma2(float2 a, float2 b, float2 c) {
    union { float2 f; unsigned long long u; } A, B, C, R;
    A.f = a; B.f = b; C.f = c;
    asm("fma.rn.f32x2 %0, %1, %2, %3;" : "=l"(R.u) : "l"(A.u), "l"(B.u), "l"(C.u));
    return R.f;
}

// ---- cp.async helpers ------------------------------------------------------
__device__ __forceinline__ uint32_t smem_u32(const void* p) {
    return (uint32_t)__cvta_generic_to_shared(p);
}
__device__ __forceinline__ void cp4(uint32_t d, const void* s) {
    asm volatile("cp.async.ca.shared.global [%0], [%1], 4;" :: "r"(d), "l"(s));
}
#define CP_COMMIT() asm volatile("cp.async.commit_group;")
#define CP_WAIT10() asm volatile("cp.async.wait_group 10;")

// prefetch ring: 16 stages, issue 12 ahead, wait leaves <=10 pending
#define RD 12

// ---------------------------------------------------------------------------
// Forward algorithm, linear domain with deferred renorm. em via cp.async ring.
// ---------------------------------------------------------------------------
template<bool AM>
__device__ __forceinline__ void fwd_loop(const float* __restrict__ em, int j,
                                         float* __restrict__ bufw,
                                         float* __restrict__ ringw,
                                         const signed char* __restrict__ mk,
                                         const float* __restrict__ startv,
                                         const float* __restrict__ endv,
                                         const float* __restrict__ trans,
                                         int b)
{
    float2 tc2[16];
    #pragma unroll
    for (int k = 0; k < 16; ++k) {
        float2 p;
        p.x = __expf(trans[(2 * k + 0) * Tn + j]) * 0.03125f;
        p.y = __expf(trans[(2 * k + 1) * Tn + j]) * 0.03125f;
        tc2[k] = p;
    }

    const uint32_t rbase = smem_u32(ringw);
    #pragma unroll
    for (int p = 1; p <= RD; ++p) {
        cp4(rbase + (((p & 15) * 32 + j) << 2), em + (size_t)p * Tn + j);
        CP_COMMIT();
    }

    float s  = __expf(startv[j] + em[j]);
    float Lr = 0.f;
    int   nm = 0;

    #pragma unroll 2
    for (int t = 1; t < Sn; ++t) {
        CP_WAIT10();
        float* sb = bufw + (t & 1) * 32;
        sb[j] = s;
        __syncwarp();
        const float emv = ringw[(t & 15) * 32 + j];
        const float ee  = __expf(emv);

        float2 a0 = {0.f, 0.f}, a1 = {0.f, 0.f}, a2 = {0.f, 0.f}, a3 = {0.f, 0.f};
        #pragma unroll
        for (int k = 0; k < 4; ++k) {
            const float4 qa = *(const float4*)(sb + 8 * k);
            const float4 qb = *(const float4*)(sb + 8 * k + 4);
            a0 = ffma2(make_float2(qa.x, qa.y), tc2[4 * k + 0], a0);
            a1 = ffma2(make_float2(qa.z, qa.w), tc2[4 * k + 1], a1);
            a2 = ffma2(make_float2(qb.x, qb.y), tc2[4 * k + 2], a2);
            a3 = ffma2(make_float2(qb.z, qb.w), tc2[4 * k + 3], a3);
        }
        const float2 a01 = fadd2(a0, a1);
        const float2 a23 = fadd2(a2, a3);
        const float2 aa  = fadd2(a01, a23);
        const float ns = (aa.x + aa.y) * ee;
        if (AM) {
            s = ns;
        } else {
            const int m_ = mk[t];
            s = m_ ? ns : s;
            nm += (m_ != 0);
        }

        // refill ring (clamped tail keeps group accounting uniform)
        const int tf = t + RD;
        const int tc = tf < Sn - 1 ? tf : Sn - 1;
        cp4(rbase + ((((tf & 15) * 32) + j) << 2), em + (size_t)tc * Tn + j);
        CP_COMMIT();

        if ((t & 15) == 15) {                           // amortized renorm
            const float r  = __shfl_sync(FULLMASK, s, 0);
            const float rr = __frcp_rn(r);
            s *= rr;
            Lr -= __logf(rr);
        }
    }
    if (AM) nm = Sn - 1;
    float v = s * __expf(endv[j]);
    #pragma unroll
    for (int off = 16; off; off >>= 1)
        v += __shfl_xor_sync(FULLMASK, v, off);
    if (j == 0) g_den[b] = (float)nm * LOG32F + Lr + __logf(v);
}

// ---------------------------------------------------------------------------
// Viterbi: pair-max + FMNMX tree (bit-exact value). First-occurrence argmax:
// descending scan for the first pair achieving the max, then the within-pair
// winner is recomputed from SMEM (vb + sTrans) off the critical path.
// ---------------------------------------------------------------------------
template<bool AM>
__device__ __forceinline__ void vit_loop(const float* __restrict__ em, int j,
                                         float* __restrict__ bufw,
                                         float* __restrict__ ringw,
                                         const signed char* __restrict__ mk,
                                         const float* __restrict__ sTrans,
                                         const float* __restrict__ startv,
                                         const float* __restrict__ endv,
                                         const float* __restrict__ trans,
                                         int b)
{
    float2 tc2[16];
    #pragma unroll
    for (int k = 0; k < 16; ++k) {
        float2 p;
        p.x = trans[(2 * k + 0) * Tn + j];
        p.y = trans[(2 * k + 1) * Tn + j];
        tc2[k] = p;
    }

    const uint32_t rbase = smem_u32(ringw);
    #pragma unroll
    for (int p = 1; p <= RD; ++p) {
        cp4(rbase + (((p & 15) * 32 + j) << 2), em + (size_t)p * Tn + j);
        CP_COMMIT();
    }

    float v = startv[j] + em[j];
    unsigned char* hb = g_hist + (size_t)b * (Sn - 1) * Tn;

    #pragma unroll 2
    for (int t = 1; t < Sn; ++t) {
        CP_WAIT10();
        float* vb = bufw + (t & 1) * 32;
        vb[j] = v;
        __syncwarp();
        const float emt = ringw[(t & 15) * 32 + j];

        float tv[16];
        #pragma unroll
        for (int k = 0; k < 8; ++k) {
            const float4 q = *(const float4*)(vb + 4 * k);
            const float2 pa = fadd2(make_float2(q.x, q.y), tc2[2 * k + 0]);
            const float2 pb = fadd2(make_float2(q.z, q.w), tc2[2 * k + 1]);
            tv[2 * k + 0] = fmaxf(pa.x, pa.y);
            tv[2 * k + 1] = fmaxf(pb.x, pb.y);
        }
        // value tree (order-independent, bit-exact)
        float u0 = fmaxf(tv[0], tv[1]),  u1 = fmaxf(tv[2], tv[3]);
        float u2 = fmaxf(tv[4], tv[5]),  u3 = fmaxf(tv[6], tv[7]);
        float u4 = fmaxf(tv[8], tv[9]),  u5 = fmaxf(tv[10], tv[11]);
        float u6 = fmaxf(tv[12], tv[13]), u7 = fmaxf(tv[14], tv[15]);
        float w0 = fmaxf(u0, u1), w1 = fmaxf(u2, u3);
        float w2 = fmaxf(u4, u5), w3 = fmaxf(u6, u7);
        const float m = fmaxf(fmaxf(w0, w1), fmaxf(w2, w3));

        // first pair index with pair-max == m (descending scan, off-chain)
        int p = 15;
        #pragma unroll
        for (int i = 14; i >= 0; --i)
            p = (tv[i] == m) ? i : p;
        // within-pair winner recomputed from SMEM (conflict-free gathers)
        const float ca = vb[2 * p]     + sTrans[(2 * p) * Tn + j];
        const float cb = vb[2 * p + 1] + sTrans[(2 * p + 1) * Tn + j];
        const int bi = 2 * p + ((cb > ca) ? 1 : 0);

        const float nv = m + emt;
        if (AM) {
            v = nv;
            hb[(size_t)(t - 1) * Tn + j] = (unsigned char)bi;
        } else {
            const int m_ = mk[t];
            const int bp = m_ ? bi : j;
            v = m_ ? nv : v;
            hb[(size_t)(t - 1) * Tn + j] = (unsigned char)bp;
        }

        const int tf = t + RD;
        const int tcl = tf < Sn - 1 ? tf : Sn - 1;
        cp4(rbase + ((((tf & 15) * 32) + j) << 2), em + (size_t)tcl * Tn + j);
        CP_COMMIT();
    }
    // last_tag = argmax_j (v_j + end_j), lowest index on ties
    float bv = v + endv[j];
    int   bidx = j;
    #pragma unroll
    for (int off = 16; off; off >>= 1) {
        const float ov = __shfl_xor_sync(FULLMASK, bv, off);
        const int   oi = __shfl_xor_sync(FULLMASK, bidx, off);
        const bool take = (ov > bv) || (ov == bv && oi < bidx);
        bv   = take ? ov : bv;
        bidx = take ? oi : bidx;
    }
    if (j == 0) g_last[b] = bidx;
}

// ---------------------------------------------------------------------------
// Main kernel: 128 CTAs x 128 threads. One CTA per SM (wave-1), one long warp
// per SMSP:
//   wid 0: fwd  batch 2*bid      wid 1: fwd  batch 2*bid+1
//   wid 2: vit  batch 2*bid      wid 3: vit  batch 2*bid+1
// ---------------------------------------------------------------------------
__global__ __launch_bounds__(128)
void crf_main_kernel(const float* __restrict__ pred,
                     const int*   __restrict__ amask,
                     const float* __restrict__ startv,
                     const float* __restrict__ endv,
                     const float* __restrict__ trans)
{
    const int wib = threadIdx.x >> 5;
    const int j   = threadIdx.x & 31;
    const int wb  = wib & 1;                 // which of the 2 batches
    const int b   = (blockIdx.x << 1) | wb;

    __shared__ __align__(16) float ring[4][16][32];
    __shared__ __align__(16) float buf[4][2][32];
    __shared__ __align__(16) float sTrans[Tn * Tn];
    __shared__ signed char mkS[2][Sn];
    __shared__ int s_allones[2];

    if (wib < 2) {
        // mask load + all-ones detect (one warp per batch)
        const int* am = amask + (size_t)b * Sn;
        int okv = 1;
        for (int t = j; t < Sn; t += 32) {
            const int mv = am[t];
            mkS[wb][t] = (signed char)mv;
            okv &= (mv == 1);
        }
        const bool ao = __all_sync(FULLMASK, okv != 0);
        if (j == 0) s_allones[wb] = ao ? 1 : 0;
    } else {
        // trans tile: warps 2,3 load 16 rows each
        const int r0 = (wib - 2) * 16;
        #pragma unroll
        for (int k = 0; k < 16; ++k)
            sTrans[(r0 + k) * Tn + j] = trans[(r0 + k) * Tn + j];
    }
    __syncthreads();

    const float* em = pred + (size_t)b * Sn * Tn;
    float* bufw  = &buf[wib][0][0];
    float* ringw = &ring[wib][0][0];

    if (wib < 2) {
        if (s_allones[wb])
            fwd_loop<true >(em, j, bufw, ringw, mkS[wb], startv, endv, trans, b);
        else
            fwd_loop<false>(em, j, bufw, ringw, mkS[wb], startv, endv, trans, b);
    } else {
        if (s_allones[wb])
            vit_loop<true >(em, j, bufw, ringw, mkS[wb], sTrans, startv, endv, trans, b);
        else
            vit_loop<false>(em, j, bufw, ringw, mkS[wb], sTrans, startv, endv, trans, b);
    }
}

// ---------------------------------------------------------------------------
// Backtrace phase 1 (+ numerator blocks): blocks 0..1023 compute per-chunk
// tag maps; blocks 1024..1087 compute the numerator (4 batches each).
// ---------------------------------------------------------------------------
__global__ __launch_bounds__(128)
void bt_phase1(const float* __restrict__ pred,
               const int*   __restrict__ amask,
               const int*   __restrict__ labels,
               const float* __restrict__ startv,
               const float* __restrict__ endv,
               const float* __restrict__ trans)
{
    const int wib  = threadIdx.x >> 5;
    const int lane = threadIdx.x & 31;

    if (blockIdx.x >= (Bn * NCH) / 4) {
        // ------- Numerator: one warp per batch ------------------------------
        const int b = ((int)blockIdx.x - (Bn * NCH) / 4) * 4 + wib;
        const float* em = pred + (size_t)b * Sn * Tn;
        const int* lab = labels + (size_t)b * Sn;
        const int* am  = amask  + (size_t)b * Sn;
        float sum = 0.f;
        int   msum = 0;
        for (int t = lane; t < Sn; t += 32) {
            const int mt = am[t];
            msum += mt;
            const int tg = lab[t];
            if (t == 0) {
                sum += startv[tg] + em[tg];
            } else {
                const int tp = lab[t - 1];
                sum += (trans[tp * Tn + tg] + em[(size_t)t * Tn + tg]) * (float)mt;
            }
        }
        #pragma unroll
        for (int off = 16; off; off >>= 1) {
            sum  += __shfl_xor_sync(FULLMASK, sum, off);
            msum += __shfl_xor_sync(FULLMASK, msum, off);
        }
        if (lane == 0) {
            const int se = msum - 1;
            const int lt = lab[se];
            g_num[b] = sum + endv[lt];
        }
        return;
    }

    const int gw = (blockIdx.x << 2) | wib;       // 0 .. Bn*NCH-1
    const int b = gw >> 6;
    const int c = gw & 63;
    const int lo = c * 32;
    int hi = lo + 31; if (hi > Sn - 2) hi = Sn - 2;
    const int n = hi - lo + 1;

    __shared__ __align__(16) unsigned char sm[4][32 * Tn];
    unsigned char* S = sm[wib];
    const uint32_t* src = (const uint32_t*)(g_hist + ((size_t)b * (Sn - 1) + lo) * Tn);
    uint32_t* dst = (uint32_t*)S;
    for (int i = lane; i < n * 8; i += 32) dst[i] = src[i];
    __syncwarp();

    int tag = lane;
    for (int k = n - 1; k >= 0; --k) tag = S[k * Tn + tag];
    g_map[b][c][lane] = (unsigned char)tag;
}

// ---------------------------------------------------------------------------
// Backtrace phase 2: per batch, compose the 64 chunk maps from the top.
// ---------------------------------------------------------------------------
__global__ __launch_bounds__(128)
void bt_phase2(float* __restrict__ out)
{
    const int wib  = threadIdx.x >> 5;
    const int lane = threadIdx.x & 31;
    const int b = (blockIdx.x << 2) | wib;

    __shared__ __align__(16) unsigned char sm[4][NCH * Tn];
    __shared__ unsigned char se[4][NCH];
    unsigned char* S = sm[wib];
    const uint32_t* src = (const uint32_t*)&g_map[b][0][0];
    uint32_t* dst = (uint32_t*)S;
    for (int i = lane; i < NCH * Tn / 4; i += 32) dst[i] = src[i];
    __syncwarp();

    if (lane == 0) {
        int e = g_last[b];
        out[(size_t)b * Sn + (Sn - 1)] = (float)e;
        for (int c = NCH - 1; c >= 0; --c) {
            se[wib][c] = (unsigned char)e;   // entry tag for chunk c
            e = S[c * Tn + e];               // exit = map[entry]
        }
    }
    __syncwarp();
    for (int c = lane; c < NCH; c += 32) g_ent[b][c] = se[wib][c];
}

// ---------------------------------------------------------------------------
// Backtrace phase 3: re-chase each chunk from its entry tag; coalesced write.
// ---------------------------------------------------------------------------
__global__ __launch_bounds__(128)
void bt_phase3(float* __restrict__ out)
{
    const int wib  = threadIdx.x >> 5;
    const int lane = threadIdx.x & 31;
    const int gw = (blockIdx.x << 2) | wib;
    const int b = gw >> 6;
    const int c = gw & 63;
    const int lo = c * 32;
    int hi = lo + 31; if (hi > Sn - 2) hi = Sn - 2;
    const int n = hi - lo + 1;

    __shared__ __align__(16) unsigned char sm[4][32 * Tn];
    __shared__ unsigned char stag[4][32];
    unsigned char* S = sm[wib];
    const uint32_t* src = (const uint32_t*)(g_hist + ((size_t)b * (Sn - 1) + lo) * Tn);
    uint32_t* dst = (uint32_t*)S;
    for (int i = lane; i < n * 8; i += 32) dst[i] = src[i];
    __syncwarp();

    if (lane == 0) {
        int tag = g_ent[b][c];
        for (int k = n - 1; k >= 0; --k) {
            tag = S[k * Tn + tag];
            stag[wib][k] = (unsigned char)tag;
        }
    }
    __syncwarp();
    if (lane < n) out[(size_t)b * Sn + lo + lane] = (float)stag[wib][lane];
}

// ---------------------------------------------------------------------------
// Loss: -mean(num - den)
// ---------------------------------------------------------------------------
__global__ void crf_loss_kernel(float* __restrict__ out)
{
    __shared__ float red[Bn];
    const int t = threadIdx.x;
    red[t] = g_num[t] - g_den[t];
    __syncthreads();
    #pragma unroll
    for (int off = 128; off; off >>= 1) {
        if (t < off) red[t] += red[t + off];
        __syncthreads();
    }
    if (t == 0) out[(size_t)Bn * Sn] = -(red[0] / (float)Bn);
}

extern "C" void kernel_launch(void* const* d_in, const int* in_sizes, int n_in,
                              void* d_out, int out_size)
{
    const float* pred   = (const float*)d_in[0];
    const int*   amask  = (const int*)  d_in[1];
    const int*   labels = (const int*)  d_in[2];
    const float* startv = (const float*)d_in[3];
    const float* endv   = (const float*)d_in[4];
    const float* trans  = (const float*)d_in[5];
    float* out = (float*)d_out;

    crf_main_kernel<<<128, 128>>>(pred, amask, startv, endv, trans);
    bt_phase1<<<(Bn * NCH) / 4 + Bn / 4, 128>>>(pred, amask, labels, startv, endv, trans);
    bt_phase2<<<Bn / 4, 128>>>(out);
    bt_phase3<<<(Bn * NCH) / 4, 128>>>(out);
    crf_loss_kernel<<<1, Bn>>>(out);
}